// round 1
// baseline (speedup 1.0000x reference)
#include <cuda_runtime.h>
#include <math.h>

#define BB 64
#define CC 100
#define TT 2000
#define KK 200
#define DD 2048

// scratch (no allocations allowed)
__device__ float g_feat_sq[2 * BB];     // ||sum_k feat||^2 per (which, b)
__device__ float g_sup_sq[BB * CC];     // sum_t (cas - pmask)^2 per (b,c)
__device__ float g_sup_cnt[BB * CC];    // sum_t pmask per (b,c)

__global__ void zero_kernel() {
    int i = blockIdx.x * blockDim.x + threadIdx.x;
    if (i < 2 * BB) g_feat_sq[i] = 0.f;
    if (i < BB * CC) { g_sup_sq[i] = 0.f; g_sup_cnt[i] = 0.f; }
}

// grid (B, 4, 2): y -> {d-part 0/1} x {k-half 0/1}; z -> act/bkg. block 256.
__global__ void feat_kernel(const float4* __restrict__ fa, const float4* __restrict__ fb) {
    const int b     = blockIdx.x;
    const int dpart = blockIdx.y & 1;
    const int khalf = blockIdx.y >> 1;
    const int which = blockIdx.z;
    const float4* __restrict__ f = which ? fb : fa;

    const int d4 = dpart * 256 + threadIdx.x;          // 0..511 (D/4)
    const int k0 = khalf * (KK / 2);
    const float4* p = f + (size_t)b * KK * (DD / 4) + (size_t)k0 * (DD / 4) + d4;

    float4 s = make_float4(0.f, 0.f, 0.f, 0.f);
#pragma unroll 8
    for (int k = 0; k < KK / 2; k++) {
        float4 v = p[(size_t)k * (DD / 4)];
        s.x += v.x; s.y += v.y; s.z += v.z; s.w += v.w;
    }
    float val = s.x * s.x + s.y * s.y + s.z * s.z + s.w * s.w;

    __shared__ float red[256];
    red[threadIdx.x] = val;
    __syncthreads();
#pragma unroll
    for (int off = 128; off > 0; off >>= 1) {
        if (threadIdx.x < off) red[threadIdx.x] += red[threadIdx.x + off];
        __syncthreads();
    }
    if (threadIdx.x == 0) atomicAdd(&g_feat_sq[which * BB + b], red[0]);
}

// NOTE: k-halves are summed via separate blocks, but the squared norm must be
// of the FULL k-sum. Fix: accumulate partial k-sums per (b,d) first is needed.
// Instead we avoid the bug by NOT splitting k: see feat_kernel_full below.
__global__ void feat_kernel_full(const float4* __restrict__ fa, const float4* __restrict__ fb) {
    const int b     = blockIdx.x;
    const int dpart = blockIdx.y;                      // 0..1
    const int which = blockIdx.z;
    const float4* __restrict__ f = which ? fb : fa;

    const int d4 = dpart * 256 + threadIdx.x;          // 0..511
    const float4* p = f + (size_t)b * KK * (DD / 4) + d4;

    float4 s = make_float4(0.f, 0.f, 0.f, 0.f);
#pragma unroll 8
    for (int k = 0; k < KK; k++) {
        float4 v = p[(size_t)k * (DD / 4)];
        s.x += v.x; s.y += v.y; s.z += v.z; s.w += v.w;
    }
    float val = s.x * s.x + s.y * s.y + s.z * s.z + s.w * s.w;

    __shared__ float red[256];
    red[threadIdx.x] = val;
    __syncthreads();
#pragma unroll
    for (int off = 128; off > 0; off >>= 1) {
        if (threadIdx.x < off) red[threadIdx.x] += red[threadIdx.x + off];
        __syncthreads();
    }
    if (threadIdx.x == 0) atomicAdd(&g_feat_sq[which * BB + b], red[0]);
}

// grid (B, 10): y -> 200-t tile. block (32, 8). Each thread owns 4 classes.
__global__ void sup_kernel(const float4* __restrict__ gt, const float4* __restrict__ cas) {
    const int b  = blockIdx.x;
    const int tb = blockIdx.y * 200;
    const int tx = threadIdx.x;   // 0..31, active < 25 (C/4)
    const int ty = threadIdx.y;   // 0..7

    float4 sq  = make_float4(0.f, 0.f, 0.f, 0.f);
    float4 cnt = make_float4(0.f, 0.f, 0.f, 0.f);

    if (tx < CC / 4) {
        const size_t base = (size_t)b * TT * (CC / 4) + (size_t)tb * (CC / 4) + tx;
#pragma unroll 5
        for (int j = 0; j < 25; j++) {
            const size_t idx = base + (size_t)(ty + 8 * j) * (CC / 4);
            float4 g = gt[idx];
            float4 c = cas[idx];
            float pm, d;
            pm = (g.x > 0.5f) ? 1.f : 0.f; d = c.x - pm; sq.x += d * d; cnt.x += pm;
            pm = (g.y > 0.5f) ? 1.f : 0.f; d = c.y - pm; sq.y += d * d; cnt.y += pm;
            pm = (g.z > 0.5f) ? 1.f : 0.f; d = c.z - pm; sq.z += d * d; cnt.z += pm;
            pm = (g.w > 0.5f) ? 1.f : 0.f; d = c.w - pm; sq.w += d * d; cnt.w += pm;
        }
    }

    __shared__ float s_sq[CC], s_cnt[CC];
    const int tid = ty * 32 + tx;
    if (tid < CC) { s_sq[tid] = 0.f; s_cnt[tid] = 0.f; }
    __syncthreads();
    if (tx < CC / 4) {
        atomicAdd(&s_sq[tx * 4 + 0], sq.x);  atomicAdd(&s_cnt[tx * 4 + 0], cnt.x);
        atomicAdd(&s_sq[tx * 4 + 1], sq.y);  atomicAdd(&s_cnt[tx * 4 + 1], cnt.y);
        atomicAdd(&s_sq[tx * 4 + 2], sq.z);  atomicAdd(&s_cnt[tx * 4 + 2], cnt.z);
        atomicAdd(&s_sq[tx * 4 + 3], sq.w);  atomicAdd(&s_cnt[tx * 4 + 3], cnt.w);
    }
    __syncthreads();
    if (tid < CC) {
        atomicAdd(&g_sup_sq[b * CC + tid], s_sq[tid]);
        atomicAdd(&g_sup_cnt[b * CC + tid], s_cnt[tid]);
    }
}

__device__ __forceinline__ float block_reduce_256(float v, float* r, int tid) {
    r[tid] = v;
    __syncthreads();
#pragma unroll
    for (int o = 128; o > 0; o >>= 1) {
        if (tid < o) r[tid] += r[tid + o];
        __syncthreads();
    }
    float res = r[0];
    __syncthreads();
    return res;
}

__global__ void finalize_kernel(const float* __restrict__ score_act,
                                const float* __restrict__ score_bkg,
                                const float* __restrict__ label,
                                float* __restrict__ out) {
    const int tid = threadIdx.x; // 256 threads
    __shared__ float rowsum[BB];
    __shared__ float r[256];

    if (tid < BB) {
        float s = 0.f;
        for (int c = 0; c < CC; c++) s += label[tid * CC + c];
        rowsum[tid] = s;
    }
    __syncthreads();

    float cls = 0.f, be = 0.f, sup = 0.f, vcnt = 0.f;
    const float invC = 1.0f / (float)CC;
    for (int i = tid; i < BB * CC; i += 256) {
        const int b = i / CC;
        const float y = label[i] / rowsum[b];
        const float p = score_act[i];
        const float lp  = fmaxf(logf(p), -100.f);
        const float l1p = fmaxf(logf(1.f - p), -100.f);
        cls -= y * lp + (1.f - y) * l1p;

        const float pb  = score_bkg[i];
        const float lpb  = fmaxf(logf(pb), -100.f);
        const float l1pb = fmaxf(logf(1.f - pb), -100.f);
        be -= invC * lpb + (1.f - invC) * l1pb;

        if (g_sup_cnt[i] > 0.f) { sup += sqrtf(g_sup_sq[i]); vcnt += 1.f; }
    }

    float um = 0.f;
    if (tid < BB) {
        const float na = sqrtf(g_feat_sq[tid]) / (float)KK;        // ||mean feat_act||
        const float nb = sqrtf(g_feat_sq[BB + tid]) / (float)KK;   // ||mean feat_bkg||
        const float la = fmaxf(100.f - na, 0.f);
        const float t  = la + nb;
        um = t * t;
    }

    const float cls_t  = block_reduce_256(cls, r, tid);
    const float be_t   = block_reduce_256(be, r, tid);
    const float sup_t  = block_reduce_256(sup, r, tid);
    const float vcnt_t = block_reduce_256(vcnt, r, tid);
    const float um_t   = block_reduce_256(um, r, tid);

    if (tid == 0) {
        const float loss = cls_t / (float)(BB * CC)
                         + 0.0005f * (um_t / (float)BB)
                         + 0.2f * (be_t / (float)(BB * CC))
                         + 1.0f * (sup_t / vcnt_t);
        out[0] = loss;
    }
}

extern "C" void kernel_launch(void* const* d_in, const int* in_sizes, int n_in,
                              void* d_out, int out_size) {
    const float*  score_act = (const float*)d_in[0];
    const float*  score_bkg = (const float*)d_in[1];
    const float4* feat_act  = (const float4*)d_in[2];
    const float4* feat_bkg  = (const float4*)d_in[3];
    const float*  label     = (const float*)d_in[4];
    const float4* gt        = (const float4*)d_in[5];
    const float4* cas       = (const float4*)d_in[6];

    zero_kernel<<<25, 256>>>();
    feat_kernel_full<<<dim3(BB, 2, 2), 256>>>(feat_act, feat_bkg);
    sup_kernel<<<dim3(BB, 10), dim3(32, 8)>>>(gt, cas);
    finalize_kernel<<<1, 256>>>(score_act, score_bkg, label, (float*)d_out);
}

// round 2
// speedup vs baseline: 1.5800x; 1.5800x over previous
#include <cuda_runtime.h>
#include <math.h>

#define BB 64
#define CC 100
#define TT 2000
#define KK 200
#define DD 2048

// scratch (no allocations allowed)
__device__ float g_feat_sq[2 * BB];     // ||sum_k feat||^2 per (which, b)
__device__ float g_sup_sq[BB * CC];     // sum_t (cas - pmask)^2 per (b,c)
__device__ float g_sup_cnt[BB * CC];    // sum_t pmask per (b,c)
__device__ float g_acc[8];              // [cls, be, sup, vcnt, um]

__global__ void zero_kernel() {
    int i = blockIdx.x * blockDim.x + threadIdx.x;
    if (i < 2 * BB) g_feat_sq[i] = 0.f;
    if (i < 8) g_acc[i] = 0.f;
    if (i < BB * CC) { g_sup_sq[i] = 0.f; g_sup_cnt[i] = 0.f; }
}

// grid (B, 2, 2): y -> d-part; z -> act/bkg. block 256. Full K per block.
__global__ void feat_kernel_full(const float4* __restrict__ fa, const float4* __restrict__ fb) {
    const int b     = blockIdx.x;
    const int dpart = blockIdx.y;                      // 0..1
    const int which = blockIdx.z;
    const float4* __restrict__ f = which ? fb : fa;

    const int d4 = dpart * 256 + threadIdx.x;          // 0..511
    const float4* p = f + (size_t)b * KK * (DD / 4) + d4;

    float4 s = make_float4(0.f, 0.f, 0.f, 0.f);
#pragma unroll 8
    for (int k = 0; k < KK; k++) {
        float4 v = p[(size_t)k * (DD / 4)];
        s.x += v.x; s.y += v.y; s.z += v.z; s.w += v.w;
    }
    float val = s.x * s.x + s.y * s.y + s.z * s.z + s.w * s.w;

    __shared__ float red[256];
    red[threadIdx.x] = val;
    __syncthreads();
#pragma unroll
    for (int off = 128; off > 0; off >>= 1) {
        if (threadIdx.x < off) red[threadIdx.x] += red[threadIdx.x + off];
        __syncthreads();
    }
    if (threadIdx.x == 0) atomicAdd(&g_feat_sq[which * BB + b], red[0]);
}

// grid (B, 10): y -> 200-t tile. block (32, 8). Each thread owns 4 classes.
__global__ void sup_kernel(const float4* __restrict__ gt, const float4* __restrict__ cas) {
    const int b  = blockIdx.x;
    const int tb = blockIdx.y * 200;
    const int tx = threadIdx.x;   // 0..31, active < 25 (C/4)
    const int ty = threadIdx.y;   // 0..7

    float4 sq  = make_float4(0.f, 0.f, 0.f, 0.f);
    float4 cnt = make_float4(0.f, 0.f, 0.f, 0.f);

    if (tx < CC / 4) {
        const size_t base = (size_t)b * TT * (CC / 4) + (size_t)tb * (CC / 4) + tx;
#pragma unroll 5
        for (int j = 0; j < 25; j++) {
            const size_t idx = base + (size_t)(ty + 8 * j) * (CC / 4);
            float4 g = gt[idx];
            float4 c = cas[idx];
            float pm, d;
            pm = (g.x > 0.5f) ? 1.f : 0.f; d = c.x - pm; sq.x += d * d; cnt.x += pm;
            pm = (g.y > 0.5f) ? 1.f : 0.f; d = c.y - pm; sq.y += d * d; cnt.y += pm;
            pm = (g.z > 0.5f) ? 1.f : 0.f; d = c.z - pm; sq.z += d * d; cnt.z += pm;
            pm = (g.w > 0.5f) ? 1.f : 0.f; d = c.w - pm; sq.w += d * d; cnt.w += pm;
        }
    }

    __shared__ float s_sq[CC], s_cnt[CC];
    const int tid = ty * 32 + tx;
    if (tid < CC) { s_sq[tid] = 0.f; s_cnt[tid] = 0.f; }
    __syncthreads();
    if (tx < CC / 4) {
        atomicAdd(&s_sq[tx * 4 + 0], sq.x);  atomicAdd(&s_cnt[tx * 4 + 0], cnt.x);
        atomicAdd(&s_sq[tx * 4 + 1], sq.y);  atomicAdd(&s_cnt[tx * 4 + 1], cnt.y);
        atomicAdd(&s_sq[tx * 4 + 2], sq.z);  atomicAdd(&s_cnt[tx * 4 + 2], cnt.z);
        atomicAdd(&s_sq[tx * 4 + 3], sq.w);  atomicAdd(&s_cnt[tx * 4 + 3], cnt.w);
    }
    __syncthreads();
    if (tid < CC) {
        atomicAdd(&g_sup_sq[b * CC + tid], s_sq[tid]);
        atomicAdd(&g_sup_cnt[b * CC + tid], s_cnt[tid]);
    }
}

// One block per batch row b. block = 128 threads (threads 0..99 own a class).
__global__ void partial_kernel(const float* __restrict__ score_act,
                               const float* __restrict__ score_bkg,
                               const float* __restrict__ label) {
    const int b   = blockIdx.x;
    const int tid = threadIdx.x;   // 0..127
    __shared__ float r[128];
    __shared__ float s_rowsum;

    const int i = b * CC + tid;
    const float lab = (tid < CC) ? label[i] : 0.f;

    // rowsum over the 100 classes
    r[tid] = lab;
    __syncthreads();
#pragma unroll
    for (int o = 64; o > 0; o >>= 1) {
        if (tid < o) r[tid] += r[tid + o];
        __syncthreads();
    }
    if (tid == 0) s_rowsum = r[0];
    __syncthreads();
    const float rowsum = s_rowsum;

    float cls = 0.f, be = 0.f, sup = 0.f, vcnt = 0.f;
    const float invC = 1.0f / (float)CC;
    if (tid < CC) {
        const float y = lab / rowsum;
        const float p = score_act[i];
        const float lp  = fmaxf(logf(p), -100.f);
        const float l1p = fmaxf(logf(1.f - p), -100.f);
        cls = -(y * lp + (1.f - y) * l1p);

        const float pb   = score_bkg[i];
        const float lpb  = fmaxf(logf(pb), -100.f);
        const float l1pb = fmaxf(logf(1.f - pb), -100.f);
        be = -(invC * lpb + (1.f - invC) * l1pb);

        if (g_sup_cnt[i] > 0.f) { sup = sqrtf(g_sup_sq[i]); vcnt = 1.f; }
    }

    // block reduce 4 values via shared (reuse r, sequential passes)
    float vals[4] = {cls, be, sup, vcnt};
#pragma unroll
    for (int v = 0; v < 4; v++) {
        __syncthreads();
        r[tid] = vals[v];
        __syncthreads();
#pragma unroll
        for (int o = 64; o > 0; o >>= 1) {
            if (tid < o) r[tid] += r[tid + o];
            __syncthreads();
        }
        vals[v] = r[0];
    }

    if (tid == 0) {
        atomicAdd(&g_acc[0], vals[0]);
        atomicAdd(&g_acc[1], vals[1]);
        atomicAdd(&g_acc[2], vals[2]);
        atomicAdd(&g_acc[3], vals[3]);
        const float na = sqrtf(g_feat_sq[b]) / (float)KK;        // ||mean feat_act||
        const float nb = sqrtf(g_feat_sq[BB + b]) / (float)KK;   // ||mean feat_bkg||
        const float la = fmaxf(100.f - na, 0.f);
        const float t  = la + nb;
        atomicAdd(&g_acc[4], t * t);
    }
}

__global__ void final_kernel(float* __restrict__ out) {
    if (threadIdx.x == 0) {
        const float loss = g_acc[0] / (float)(BB * CC)
                         + 0.0005f * (g_acc[4] / (float)BB)
                         + 0.2f * (g_acc[1] / (float)(BB * CC))
                         + 1.0f * (g_acc[2] / g_acc[3]);
        out[0] = loss;
    }
}

extern "C" void kernel_launch(void* const* d_in, const int* in_sizes, int n_in,
                              void* d_out, int out_size) {
    const float*  score_act = (const float*)d_in[0];
    const float*  score_bkg = (const float*)d_in[1];
    const float4* feat_act  = (const float4*)d_in[2];
    const float4* feat_bkg  = (const float4*)d_in[3];
    const float*  label     = (const float*)d_in[4];
    const float4* gt        = (const float4*)d_in[5];
    const float4* cas       = (const float4*)d_in[6];

    zero_kernel<<<25, 256>>>();
    feat_kernel_full<<<dim3(BB, 2, 2), 256>>>(feat_act, feat_bkg);
    sup_kernel<<<dim3(BB, 10), dim3(32, 8)>>>(gt, cas);
    partial_kernel<<<BB, 128>>>(score_act, score_bkg, label);
    final_kernel<<<1, 32>>>((float*)d_out);
}

// round 3
// speedup vs baseline: 1.6342x; 1.0343x over previous
#include <cuda_runtime.h>
#include <math.h>

#define BB 64
#define CC 100
#define TT 2000
#define KK 200
#define DD 2048
#define NTILE 10   // t-tiles in sup kernel

// Deterministic partial buffers — written (not accumulated), so no zeroing needed.
__device__ float g_feat_part[2 * BB * 2];          // [which][b][dpart]
__device__ float g_sup_sq_p[BB * NTILE * CC];      // [b][tile][c]
__device__ float g_sup_cnt_p[BB * NTILE * CC];     // [b][tile][c]
__device__ float g_bce[BB * 2];                    // [b][{cls,be}]
__device__ float g_row[BB * 3];                    // [b][{sup, vcnt, um}]

// grid (B, 2, 2): y -> d-part; z -> act/bkg. block 256. Full K per block.
__global__ void feat_kernel(const float4* __restrict__ fa, const float4* __restrict__ fb) {
    const int b     = blockIdx.x;
    const int dpart = blockIdx.y;                      // 0..1
    const int which = blockIdx.z;
    const float4* __restrict__ f = which ? fb : fa;

    const int d4 = dpart * 256 + threadIdx.x;          // 0..511
    const float4* p = f + (size_t)b * KK * (DD / 4) + d4;

    float4 s = make_float4(0.f, 0.f, 0.f, 0.f);
#pragma unroll 8
    for (int k = 0; k < KK; k++) {
        float4 v = p[(size_t)k * (DD / 4)];
        s.x += v.x; s.y += v.y; s.z += v.z; s.w += v.w;
    }
    float val = s.x * s.x + s.y * s.y + s.z * s.z + s.w * s.w;

    __shared__ float red[256];
    red[threadIdx.x] = val;
    __syncthreads();
#pragma unroll
    for (int off = 128; off > 0; off >>= 1) {
        if (threadIdx.x < off) red[threadIdx.x] += red[threadIdx.x + off];
        __syncthreads();
    }
    if (threadIdx.x == 0) g_feat_part[which * (BB * 2) + b * 2 + dpart] = red[0];
}

// grid (B, 11): y<10 -> 200-t tile of gt/cas; y==10 -> BCE for row b. block (32, 8).
__global__ void sup_bce_kernel(const float4* __restrict__ gt, const float4* __restrict__ cas,
                               const float* __restrict__ score_act,
                               const float* __restrict__ score_bkg,
                               const float* __restrict__ label) {
    const int b   = blockIdx.x;
    const int tx  = threadIdx.x;   // 0..31
    const int ty  = threadIdx.y;   // 0..7
    const int tid = ty * 32 + tx;

    if (blockIdx.y == NTILE) {
        // ---- BCE partials for row b (runs concurrently with memory tiles) ----
        __shared__ float r[128];
        __shared__ float s_rowsum;
        if (tid >= 128) return;
        const int i = b * CC + tid;
        const float lab = (tid < CC) ? label[i] : 0.f;

        r[tid] = lab;
        __syncthreads();
#pragma unroll
        for (int o = 64; o > 0; o >>= 1) {
            if (tid < o) r[tid] += r[tid + o];
            __syncthreads();
        }
        if (tid == 0) s_rowsum = r[0];
        __syncthreads();
        const float rowsum = s_rowsum;

        float cls = 0.f, be = 0.f;
        const float invC = 1.0f / (float)CC;
        if (tid < CC) {
            const float y = lab / rowsum;
            const float p = score_act[i];
            cls = -(y * fmaxf(logf(p), -100.f) + (1.f - y) * fmaxf(logf(1.f - p), -100.f));
            const float pb = score_bkg[i];
            be = -(invC * fmaxf(logf(pb), -100.f) + (1.f - invC) * fmaxf(logf(1.f - pb), -100.f));
        }
        // reduce cls, be
        __syncthreads();
        r[tid] = cls;
        __syncthreads();
#pragma unroll
        for (int o = 64; o > 0; o >>= 1) {
            if (tid < o) r[tid] += r[tid + o];
            __syncthreads();
        }
        if (tid == 0) g_bce[b * 2 + 0] = r[0];
        __syncthreads();
        r[tid] = be;
        __syncthreads();
#pragma unroll
        for (int o = 64; o > 0; o >>= 1) {
            if (tid < o) r[tid] += r[tid + o];
            __syncthreads();
        }
        if (tid == 0) g_bce[b * 2 + 1] = r[0];
        return;
    }

    // ---- sup tile: 200 time-steps of (cas - pmask)^2 and pmask count ----
    const int tb = blockIdx.y * 200;

    float4 sq  = make_float4(0.f, 0.f, 0.f, 0.f);
    float4 cnt = make_float4(0.f, 0.f, 0.f, 0.f);

    if (tx < CC / 4) {
        const size_t base = (size_t)b * TT * (CC / 4) + (size_t)tb * (CC / 4) + tx;
#pragma unroll 5
        for (int j = 0; j < 25; j++) {
            const size_t idx = base + (size_t)(ty + 8 * j) * (CC / 4);
            float4 g = gt[idx];
            float4 c = cas[idx];
            float pm, d;
            pm = (g.x > 0.5f) ? 1.f : 0.f; d = c.x - pm; sq.x += d * d; cnt.x += pm;
            pm = (g.y > 0.5f) ? 1.f : 0.f; d = c.y - pm; sq.y += d * d; cnt.y += pm;
            pm = (g.z > 0.5f) ? 1.f : 0.f; d = c.z - pm; sq.z += d * d; cnt.z += pm;
            pm = (g.w > 0.5f) ? 1.f : 0.f; d = c.w - pm; sq.w += d * d; cnt.w += pm;
        }
    }

    __shared__ float s_sq[CC], s_cnt[CC];
    if (tid < CC) { s_sq[tid] = 0.f; s_cnt[tid] = 0.f; }
    __syncthreads();
    if (tx < CC / 4) {
        atomicAdd(&s_sq[tx * 4 + 0], sq.x);  atomicAdd(&s_cnt[tx * 4 + 0], cnt.x);
        atomicAdd(&s_sq[tx * 4 + 1], sq.y);  atomicAdd(&s_cnt[tx * 4 + 1], cnt.y);
        atomicAdd(&s_sq[tx * 4 + 2], sq.z);  atomicAdd(&s_cnt[tx * 4 + 2], cnt.z);
        atomicAdd(&s_sq[tx * 4 + 3], sq.w);  atomicAdd(&s_cnt[tx * 4 + 3], cnt.w);
    }
    __syncthreads();
    if (tid < CC) {
        const int o = b * (NTILE * CC) + blockIdx.y * CC + tid;
        g_sup_sq_p[o]  = s_sq[tid];
        g_sup_cnt_p[o] = s_cnt[tid];
    }
}

// grid = 64, block = 128. Per-row finalize with shuffle reductions.
__global__ void row_finalize_kernel() {
    const int b   = blockIdx.x;
    const int tid = threadIdx.x;    // 0..127
    const int lane = tid & 31, wrp = tid >> 5;

    float sup = 0.f, vcnt = 0.f;
    if (tid < CC) {
        float sq = 0.f, cnt = 0.f;
        const int base = b * (NTILE * CC) + tid;
#pragma unroll
        for (int t = 0; t < NTILE; t++) {
            sq  += g_sup_sq_p[base + t * CC];
            cnt += g_sup_cnt_p[base + t * CC];
        }
        if (cnt > 0.f) { sup = sqrtf(sq); vcnt = 1.f; }
    }

#pragma unroll
    for (int o = 16; o > 0; o >>= 1) {
        sup  += __shfl_down_sync(0xffffffff, sup, o);
        vcnt += __shfl_down_sync(0xffffffff, vcnt, o);
    }
    __shared__ float s_sup[4], s_vcnt[4];
    if (lane == 0) { s_sup[wrp] = sup; s_vcnt[wrp] = vcnt; }
    __syncthreads();
    if (tid == 0) {
        float st = s_sup[0] + s_sup[1] + s_sup[2] + s_sup[3];
        float vt = s_vcnt[0] + s_vcnt[1] + s_vcnt[2] + s_vcnt[3];
        const float na = sqrtf(g_feat_part[b * 2] + g_feat_part[b * 2 + 1]) / (float)KK;
        const float nb = sqrtf(g_feat_part[BB * 2 + b * 2] + g_feat_part[BB * 2 + b * 2 + 1]) / (float)KK;
        const float la = fmaxf(100.f - na, 0.f);
        const float t  = la + nb;
        g_row[b * 3 + 0] = st;
        g_row[b * 3 + 1] = vt;
        g_row[b * 3 + 2] = t * t;
    }
}

// 1 block, 64 threads: final combine.
__global__ void final_kernel(float* __restrict__ out) {
    const int tid = threadIdx.x;  // 0..63
    float cls = g_bce[tid * 2 + 0];
    float be  = g_bce[tid * 2 + 1];
    float sup = g_row[tid * 3 + 0];
    float vct = g_row[tid * 3 + 1];
    float um  = g_row[tid * 3 + 2];

    const int lane = tid & 31, wrp = tid >> 5;
#pragma unroll
    for (int o = 16; o > 0; o >>= 1) {
        cls += __shfl_down_sync(0xffffffff, cls, o);
        be  += __shfl_down_sync(0xffffffff, be,  o);
        sup += __shfl_down_sync(0xffffffff, sup, o);
        vct += __shfl_down_sync(0xffffffff, vct, o);
        um  += __shfl_down_sync(0xffffffff, um,  o);
    }
    __shared__ float s[2][5];
    if (lane == 0) { s[wrp][0] = cls; s[wrp][1] = be; s[wrp][2] = sup; s[wrp][3] = vct; s[wrp][4] = um; }
    __syncthreads();
    if (tid == 0) {
        const float loss = (s[0][0] + s[1][0]) / (float)(BB * CC)
                         + 0.0005f * ((s[0][4] + s[1][4]) / (float)BB)
                         + 0.2f * ((s[0][1] + s[1][1]) / (float)(BB * CC))
                         + 1.0f * ((s[0][2] + s[1][2]) / (s[0][3] + s[1][3]));
        out[0] = loss;
    }
}

extern "C" void kernel_launch(void* const* d_in, const int* in_sizes, int n_in,
                              void* d_out, int out_size) {
    const float*  score_act = (const float*)d_in[0];
    const float*  score_bkg = (const float*)d_in[1];
    const float4* feat_act  = (const float4*)d_in[2];
    const float4* feat_bkg  = (const float4*)d_in[3];
    const float*  label     = (const float*)d_in[4];
    const float4* gt        = (const float4*)d_in[5];
    const float4* cas       = (const float4*)d_in[6];

    feat_kernel<<<dim3(BB, 2, 2), 256>>>(feat_act, feat_bkg);
    sup_bce_kernel<<<dim3(BB, NTILE + 1), dim3(32, 8)>>>(gt, cas, score_act, score_bkg, label);
    row_finalize_kernel<<<BB, 128>>>();
    final_kernel<<<1, 64>>>((float*)d_out);
}

// round 4
// speedup vs baseline: 1.8568x; 1.1362x over previous
#include <cuda_runtime.h>
#include <math.h>

#define BB 64
#define CC 100
#define TT 2000
#define KK 200
#define DD 2048
#define NTILE 10

#define SUP_BLOCKS  (BB * NTILE)          // 640
#define FEAT_BLOCKS (BB * 2 * 2)          // 256
#define BCE_BLOCKS  (BB)                  // 64
#define TOTAL_BLOCKS (SUP_BLOCKS + FEAT_BLOCKS + BCE_BLOCKS)  // 960

// Deterministic partial buffers — written (not accumulated), no zeroing needed.
__device__ float g_feat_part[2 * BB * 2];          // [which][b][dpart]
__device__ float g_sup_sq_p[BB * NTILE * CC];      // [b][tile][c]
__device__ float g_sup_cnt_p[BB * NTILE * CC];     // [b][tile][c]
__device__ float g_bce[BB * 2];                    // [b][{cls,be}]
__device__ float g_row[BB * 3];                    // [b][{sup, vcnt, um}]
__device__ unsigned int g_done = 0;                // reset after each use

// ── mega kernel: 960 blocks × 256 threads ─────────────────────────────────
__global__ void __launch_bounds__(256) mega_kernel(
        const float4* __restrict__ fa, const float4* __restrict__ fb,
        const float4* __restrict__ gt, const float4* __restrict__ cas,
        const float* __restrict__ score_act,
        const float* __restrict__ score_bkg,
        const float* __restrict__ label) {
    const int blk = blockIdx.x;
    const int tid = threadIdx.x;       // 0..255
    const int tx  = tid & 31;
    const int ty  = tid >> 5;          // 0..7

    if (blk < SUP_BLOCKS) {
        // ---- sup tile: (b, tile) over 200 time steps ----
        const int b    = blk / NTILE;
        const int tile = blk % NTILE;
        const int tb   = tile * 200;

        float4 sq  = make_float4(0.f, 0.f, 0.f, 0.f);
        float4 cnt = make_float4(0.f, 0.f, 0.f, 0.f);

        if (tx < CC / 4) {
            const size_t base = (size_t)b * TT * (CC / 4) + (size_t)tb * (CC / 4) + tx;
#pragma unroll 5
            for (int j = 0; j < 25; j++) {
                const size_t idx = base + (size_t)(ty + 8 * j) * (CC / 4);
                float4 g = gt[idx];
                float4 c = cas[idx];
                float pm, d;
                pm = (g.x > 0.5f) ? 1.f : 0.f; d = c.x - pm; sq.x += d * d; cnt.x += pm;
                pm = (g.y > 0.5f) ? 1.f : 0.f; d = c.y - pm; sq.y += d * d; cnt.y += pm;
                pm = (g.z > 0.5f) ? 1.f : 0.f; d = c.z - pm; sq.z += d * d; cnt.z += pm;
                pm = (g.w > 0.5f) ? 1.f : 0.f; d = c.w - pm; sq.w += d * d; cnt.w += pm;
            }
        }

        __shared__ float s_sq[CC], s_cnt[CC];
        if (tid < CC) { s_sq[tid] = 0.f; s_cnt[tid] = 0.f; }
        __syncthreads();
        if (tx < CC / 4) {
            atomicAdd(&s_sq[tx * 4 + 0], sq.x);  atomicAdd(&s_cnt[tx * 4 + 0], cnt.x);
            atomicAdd(&s_sq[tx * 4 + 1], sq.y);  atomicAdd(&s_cnt[tx * 4 + 1], cnt.y);
            atomicAdd(&s_sq[tx * 4 + 2], sq.z);  atomicAdd(&s_cnt[tx * 4 + 2], cnt.z);
            atomicAdd(&s_sq[tx * 4 + 3], sq.w);  atomicAdd(&s_cnt[tx * 4 + 3], cnt.w);
        }
        __syncthreads();
        if (tid < CC) {
            const int o = b * (NTILE * CC) + tile * CC + tid;
            g_sup_sq_p[o]  = s_sq[tid];
            g_sup_cnt_p[o] = s_cnt[tid];
        }
        return;
    }

    if (blk < SUP_BLOCKS + FEAT_BLOCKS) {
        // ---- feat: (which, b, dpart), full K reduce per (b,d) ----
        const int idx   = blk - SUP_BLOCKS;      // 0..255
        const int which = idx >> 7;              // 0..1
        const int rem   = idx & 127;
        const int b     = rem >> 1;              // 0..63
        const int dpart = rem & 1;               // 0..1
        const float4* __restrict__ f = which ? fb : fa;

        const int d4 = dpart * 256 + tid;        // 0..511
        const float4* p = f + (size_t)b * KK * (DD / 4) + d4;

        float4 s = make_float4(0.f, 0.f, 0.f, 0.f);
#pragma unroll 8
        for (int k = 0; k < KK; k++) {
            float4 v = p[(size_t)k * (DD / 4)];
            s.x += v.x; s.y += v.y; s.z += v.z; s.w += v.w;
        }
        float val = s.x * s.x + s.y * s.y + s.z * s.z + s.w * s.w;

        __shared__ float red[256];
        red[tid] = val;
        __syncthreads();
#pragma unroll
        for (int off = 128; off > 0; off >>= 1) {
            if (tid < off) red[tid] += red[tid + off];
            __syncthreads();
        }
        if (tid == 0) g_feat_part[which * (BB * 2) + b * 2 + dpart] = red[0];
        return;
    }

    // ---- BCE partials for row b ----
    {
        const int b = blk - SUP_BLOCKS - FEAT_BLOCKS;
        if (tid >= 128) return;
        __shared__ float r[128];
        __shared__ float s_rowsum;
        const int i = b * CC + tid;
        const float lab = (tid < CC) ? label[i] : 0.f;

        r[tid] = lab;
        __syncthreads();
#pragma unroll
        for (int o = 64; o > 0; o >>= 1) {
            if (tid < o) r[tid] += r[tid + o];
            __syncthreads();
        }
        if (tid == 0) s_rowsum = r[0];
        __syncthreads();
        const float rowsum = s_rowsum;

        float cls = 0.f, be = 0.f;
        const float invC = 1.0f / (float)CC;
        if (tid < CC) {
            const float y = lab / rowsum;
            const float p = score_act[i];
            cls = -(y * fmaxf(logf(p), -100.f) + (1.f - y) * fmaxf(logf(1.f - p), -100.f));
            const float pb = score_bkg[i];
            be = -(invC * fmaxf(logf(pb), -100.f) + (1.f - invC) * fmaxf(logf(1.f - pb), -100.f));
        }
        __syncthreads();
        r[tid] = cls;
        __syncthreads();
#pragma unroll
        for (int o = 64; o > 0; o >>= 1) {
            if (tid < o) r[tid] += r[tid + o];
            __syncthreads();
        }
        if (tid == 0) g_bce[b * 2 + 0] = r[0];
        __syncthreads();
        r[tid] = be;
        __syncthreads();
#pragma unroll
        for (int o = 64; o > 0; o >>= 1) {
            if (tid < o) r[tid] += r[tid + o];
            __syncthreads();
        }
        if (tid == 0) g_bce[b * 2 + 1] = r[0];
    }
}

// ── finalize: 64 blocks × 128 threads; last block does the global combine ──
__global__ void __launch_bounds__(128) finalize_kernel(float* __restrict__ out) {
    const int b    = blockIdx.x;
    const int tid  = threadIdx.x;
    const int lane = tid & 31, wrp = tid >> 5;
    __shared__ float s_sup[4], s_vcnt[4];
    __shared__ bool  s_last;

    float sup = 0.f, vcnt = 0.f;
    if (tid < CC) {
        float sq = 0.f, cnt = 0.f;
        const int base = b * (NTILE * CC) + tid;
#pragma unroll
        for (int t = 0; t < NTILE; t++) {
            sq  += g_sup_sq_p[base + t * CC];
            cnt += g_sup_cnt_p[base + t * CC];
        }
        if (cnt > 0.f) { sup = sqrtf(sq); vcnt = 1.f; }
    }
#pragma unroll
    for (int o = 16; o > 0; o >>= 1) {
        sup  += __shfl_down_sync(0xffffffff, sup, o);
        vcnt += __shfl_down_sync(0xffffffff, vcnt, o);
    }
    if (lane == 0) { s_sup[wrp] = sup; s_vcnt[wrp] = vcnt; }
    __syncthreads();
    if (tid == 0) {
        g_row[b * 3 + 0] = s_sup[0] + s_sup[1] + s_sup[2] + s_sup[3];
        g_row[b * 3 + 1] = s_vcnt[0] + s_vcnt[1] + s_vcnt[2] + s_vcnt[3];
        const float na = sqrtf(g_feat_part[b * 2] + g_feat_part[b * 2 + 1]) / (float)KK;
        const float nb = sqrtf(g_feat_part[BB * 2 + b * 2] + g_feat_part[BB * 2 + b * 2 + 1]) / (float)KK;
        const float la = fmaxf(100.f - na, 0.f);
        const float t  = la + nb;
        g_row[b * 3 + 2] = t * t;
        __threadfence();
        const unsigned int prev = atomicAdd(&g_done, 1u);
        s_last = (prev == BB - 1);
    }
    __syncthreads();
    if (!s_last) return;

    // last block: fixed-order combine over all 64 rows (deterministic)
    if (tid < BB) {
        float cls = g_bce[tid * 2 + 0];
        float be  = g_bce[tid * 2 + 1];
        float st  = g_row[tid * 3 + 0];
        float vt  = g_row[tid * 3 + 1];
        float um  = g_row[tid * 3 + 2];
#pragma unroll
        for (int o = 16; o > 0; o >>= 1) {
            cls += __shfl_down_sync(0xffffffff, cls, o);
            be  += __shfl_down_sync(0xffffffff, be,  o);
            st  += __shfl_down_sync(0xffffffff, st,  o);
            vt  += __shfl_down_sync(0xffffffff, vt,  o);
            um  += __shfl_down_sync(0xffffffff, um,  o);
        }
        __shared__ float s[2][5];
        if (lane == 0) { s[wrp][0] = cls; s[wrp][1] = be; s[wrp][2] = st; s[wrp][3] = vt; s[wrp][4] = um; }
        __syncwarp();
        if (tid == 32) { /* warp1 lane0 stored */ }
        __syncthreads();
        if (tid == 0) {
            const float loss = (s[0][0] + s[1][0]) / (float)(BB * CC)
                             + 0.0005f * ((s[0][4] + s[1][4]) / (float)BB)
                             + 0.2f * ((s[0][1] + s[1][1]) / (float)(BB * CC))
                             + 1.0f * ((s[0][2] + s[1][2]) / (s[0][3] + s[1][3]));
            out[0] = loss;
            g_done = 0;   // reset for next graph replay
        }
    } else {
        __syncthreads();
    }
}

extern "C" void kernel_launch(void* const* d_in, const int* in_sizes, int n_in,
                              void* d_out, int out_size) {
    const float*  score_act = (const float*)d_in[0];
    const float*  score_bkg = (const float*)d_in[1];
    const float4* feat_act  = (const float4*)d_in[2];
    const float4* feat_bkg  = (const float4*)d_in[3];
    const float*  label     = (const float*)d_in[4];
    const float4* gt        = (const float4*)d_in[5];
    const float4* cas       = (const float4*)d_in[6];

    mega_kernel<<<TOTAL_BLOCKS, 256>>>(feat_act, feat_bkg, gt, cas,
                                       score_act, score_bkg, label);
    finalize_kernel<<<BB, 128>>>((float*)d_out);
}